// round 1
// baseline (speedup 1.0000x reference)
#include <cuda_runtime.h>
#include <cstdint>
#include <math.h>

// Problem constants (fixed by the dataset)
#define NTOT 100000
#define N0C  30000
#define RC   6

typedef unsigned long long ull;

// ---------------- scratch (device globals; no allocations allowed) ------------
// g_h  : concatenated projected features           [100000 x 128]
// g_B1 : [W1(r=0..5) | root1] combined             [128 x 448]
// g_z1 : layer-1: cols 0..383 = xt per relation, cols 384..447 = layer-1 output
// g_B2 : [W2(r=0..5) | root2] combined             [64 x 112]
// g_z2 : layer-2: cols 0..95 = xt per relation, cols 96..111 = layer-2 output
__device__ __align__(128) float g_h [(size_t)NTOT * 128];
__device__ __align__(128) float g_B1[128 * 448];
__device__ __align__(128) float g_bias1e[448];
__device__ __align__(128) float g_z1[(size_t)NTOT * 448];
__device__ __align__(128) float g_B2[64 * 112];
__device__ __align__(128) float g_bias2e[112];
__device__ __align__(128) float g_z2[(size_t)NTOT * 112];
__device__ __align__(128) int   g_cnt [RC * NTOT];
__device__ __align__(128) float g_invc[RC * NTOT];

// ---------------- tiny init kernels ------------------------------------------
__global__ void k_zero_cnt() {
    int i = blockIdx.x * 256 + threadIdx.x;
    if (i < RC * NTOT) g_cnt[i] = 0;
}

// B1[k, c] : c<384 -> W1[r=c/64][k][c%64] = sum_b comp1[r,b]*bases1[b,k,o]
//            c>=384 -> root1[k][c-384]
__global__ void k_build_B1(const float* __restrict__ comp1,
                           const float* __restrict__ bases1,
                           const float* __restrict__ root1,
                           const float* __restrict__ bias1) {
    int i = blockIdx.x * 256 + threadIdx.x;
    if (i >= 128 * 448) return;
    int k = i / 448, c = i % 448;
    float v;
    if (c < 384) {
        int r = c >> 6, o = c & 63;
        float s = 0.f;
        #pragma unroll
        for (int b = 0; b < 30; b++)
            s += comp1[r * 30 + b] * bases1[b * 8192 + k * 64 + o];
        v = s;
    } else {
        v = root1[k * 64 + (c - 384)];
    }
    g_B1[k * 448 + c] = v;
    if (k == 0) g_bias1e[c] = (c < 384) ? 0.f : bias1[c - 384];
}

__global__ void k_build_B2(const float* __restrict__ comp2,
                           const float* __restrict__ bases2,
                           const float* __restrict__ root2,
                           const float* __restrict__ bias2) {
    int i = blockIdx.x * 256 + threadIdx.x;
    if (i >= 64 * 112) return;
    int k = i / 112, c = i % 112;
    float v;
    if (c < 96) {
        int r = c >> 4, o = c & 15;
        float s = 0.f;
        #pragma unroll
        for (int b = 0; b < 30; b++)
            s += comp2[r * 30 + b] * bases2[b * 1024 + k * 16 + o];
        v = s;
    } else {
        v = root2[k * 16 + (c - 96)];
    }
    g_B2[k * 112 + c] = v;
    if (k == 0) g_bias2e[c] = (c < 96) ? 0.f : bias2[c - 96];
}

__global__ void k_count(const int* __restrict__ dst, const int* __restrict__ et, int E) {
    int e = blockIdx.x * 256 + threadIdx.x;
    if (e >= E) return;
    atomicAdd(&g_cnt[et[e] * NTOT + dst[e]], 1);
}

__global__ void k_invc() {
    int i = blockIdx.x * 256 + threadIdx.x;
    if (i >= RC * NTOT) return;
    int c = g_cnt[i];
    g_invc[i] = 1.0f / (float)(c > 0 ? c : 1);
}

// ---------------- fp32x2 GEMM -------------------------------------------------
// C[M,N] = A[M,K] * B + bias   (row-major A, lda; row-major C, ldc)
// bt==0 : B is [K,N] row-major (ldb = row stride)
// bt==1 : B is [N,K] row-major (C = A * B^T, ldb = K-stride)
// Tile: BM=128, BN=64, BK=16; 256 threads; per-thread 8x4 via fma.rn.f32x2.
__device__ __forceinline__ void ffma2(ull& c, ull a, ull b) {
    asm("fma.rn.f32x2 %0, %1, %2, %0;" : "+l"(c) : "l"(a), "l"(b));
}

__global__ __launch_bounds__(256) void k_gemm(
    int M, int N, int K,
    const float* __restrict__ A, int lda,
    const float* __restrict__ B, int ldb,
    float* __restrict__ C, int ldc,
    const float* __restrict__ bias, int bt)
{
    __shared__ float As2[16 * 256];  // A duplicated pairs: As2[k][2*m], As2[k][2*m+1]
    __shared__ float Bs[16 * 64];

    int tid = threadIdx.x;
    int tx = tid & 15, ty = tid >> 4;
    int tx4 = tx * 4, ty8 = ty * 8;
    int rowBase = blockIdx.y * 128;
    int colBase = blockIdx.x * 64;

    ull acc[8][2];
    #pragma unroll
    for (int i = 0; i < 8; i++) { acc[i][0] = 0ull; acc[i][1] = 0ull; }

    int lr  = tid >> 1;          // 0..127 : A tile row
    int lkh = (tid & 1) * 8;     // 0 or 8 : A tile k-half
    int arow = rowBase + lr;

    for (int kt = 0; kt < K; kt += 16) {
        // --- load A tile (zero-fill OOB rows), store duplicated pairs ---
        float4 v0, v1;
        if (arow < M) {
            const float4* ap = (const float4*)(A + (size_t)arow * lda + kt + lkh);
            v0 = ap[0]; v1 = ap[1];
        } else {
            v0 = make_float4(0.f, 0.f, 0.f, 0.f); v1 = v0;
        }
        {
            float av[8] = {v0.x, v0.y, v0.z, v0.w, v1.x, v1.y, v1.z, v1.w};
            #pragma unroll
            for (int j = 0; j < 8; j++)
                *(float2*)&As2[(lkh + j) * 256 + 2 * lr] = make_float2(av[j], av[j]);
        }
        // --- load B tile ---
        if (bt == 0) {
            int kk = tid >> 4, n4 = (tid & 15) * 4;
            int gc = colBase + n4;
            float4 v = make_float4(0.f, 0.f, 0.f, 0.f);
            if (gc < N) v = *(const float4*)(B + (size_t)(kt + kk) * ldb + gc);
            *(float4*)&Bs[kk * 64 + n4] = v;
        } else {
            int n = tid >> 2, k4 = (tid & 3) * 4;
            int gc = colBase + n;
            float4 v = make_float4(0.f, 0.f, 0.f, 0.f);
            if (gc < N) v = *(const float4*)(B + (size_t)gc * ldb + kt + k4);
            Bs[(k4 + 0) * 64 + n] = v.x;
            Bs[(k4 + 1) * 64 + n] = v.y;
            Bs[(k4 + 2) * 64 + n] = v.z;
            Bs[(k4 + 3) * 64 + n] = v.w;
        }
        __syncthreads();
        // --- compute ---
        #pragma unroll
        for (int k = 0; k < 16; k++) {
            ull b01 = *(const ull*)&Bs[k * 64 + tx4];
            ull b23 = *(const ull*)&Bs[k * 64 + tx4 + 2];
            const float* ar = &As2[k * 256 + 2 * ty8];
            #pragma unroll
            for (int i = 0; i < 8; i++) {
                ull a = *(const ull*)&ar[2 * i];
                ffma2(acc[i][0], a, b01);
                ffma2(acc[i][1], a, b23);
            }
        }
        __syncthreads();
    }

    // --- epilogue: unpack, add bias, store ---
    int col = colBase + tx4;
    if (col < N) {
        float bb0 = bias[col], bb1 = bias[col + 1], bb2 = bias[col + 2], bb3 = bias[col + 3];
        #pragma unroll
        for (int i = 0; i < 8; i++) {
            int gr = rowBase + ty8 + i;
            if (gr < M) {
                float lo0, hi0, lo1, hi1;
                asm("mov.b64 {%0,%1}, %2;" : "=f"(lo0), "=f"(hi0) : "l"(acc[i][0]));
                asm("mov.b64 {%0,%1}, %2;" : "=f"(lo1), "=f"(hi1) : "l"(acc[i][1]));
                float4 o = make_float4(lo0 + bb0, hi0 + bb1, lo1 + bb2, hi1 + bb3);
                *(float4*)(C + (size_t)gr * ldc + col) = o;
            }
        }
    }
}

// ---------------- edge scatter (mean folded in via 1/cnt) ---------------------
// Layer 1: 16 lanes per edge, each moves one float4 (64 floats total).
// Adds xt1[et][src]/cnt into g_z1[dst, 384..447]  (read cols 0..383, write 384..447: disjoint)
__global__ __launch_bounds__(256) void k_scatter1(
    const int* __restrict__ src, const int* __restrict__ dst,
    const int* __restrict__ et, int E)
{
    int gid = blockIdx.x * 256 + threadIdx.x;
    int e = gid >> 4;
    if (e >= E) return;
    int q = gid & 15;
    int s = src[e], d = dst[e], r = et[e];
    float ic = g_invc[r * NTOT + d];
    float4 v = *(const float4*)(g_z1 + (size_t)s * 448 + r * 64 + q * 4);
    float* p = g_z1 + (size_t)d * 448 + 384 + q * 4;
    asm volatile("red.global.add.v4.f32 [%0], {%1,%2,%3,%4};"
                 :: "l"(p), "f"(v.x * ic), "f"(v.y * ic), "f"(v.z * ic), "f"(v.w * ic)
                 : "memory");
}

// Layer 2: 4 lanes per edge, only dst < N0C matters for the output.
__global__ __launch_bounds__(256) void k_scatter2(
    const int* __restrict__ src, const int* __restrict__ dst,
    const int* __restrict__ et, int E)
{
    int gid = blockIdx.x * 256 + threadIdx.x;
    int e = gid >> 2;
    if (e >= E) return;
    int d = dst[e];
    if (d >= N0C) return;
    int q = gid & 3;
    int s = src[e], r = et[e];
    float ic = g_invc[r * NTOT + d];
    float4 v = *(const float4*)(g_z2 + (size_t)s * 112 + r * 16 + q * 4);
    float* p = g_z2 + (size_t)d * 112 + 96 + q * 4;
    asm volatile("red.global.add.v4.f32 [%0], {%1,%2,%3,%4};"
                 :: "l"(p), "f"(v.x * ic), "f"(v.y * ic), "f"(v.z * ic), "f"(v.w * ic)
                 : "memory");
}

// ---------------- softmax over the 16 logits of the first 30000 rows ----------
__global__ void k_softmax(float* __restrict__ out) {
    int n = blockIdx.x * 256 + threadIdx.x;
    if (n >= N0C) return;
    const float* row = g_z2 + (size_t)n * 112 + 96;
    float v[16];
    #pragma unroll
    for (int j = 0; j < 16; j += 4) {
        float4 t = *(const float4*)(row + j);
        v[j] = t.x; v[j + 1] = t.y; v[j + 2] = t.z; v[j + 3] = t.w;
    }
    float m = v[0];
    #pragma unroll
    for (int j = 1; j < 16; j++) m = fmaxf(m, v[j]);
    float s = 0.f;
    #pragma unroll
    for (int j = 0; j < 16; j++) { v[j] = expf(v[j] - m); s += v[j]; }
    float is = 1.f / s;
    #pragma unroll
    for (int j = 0; j < 16; j += 4) {
        float4 o = make_float4(v[j] * is, v[j + 1] * is, v[j + 2] * is, v[j + 3] * is);
        *(float4*)(out + (size_t)n * 16 + j) = o;
    }
}

// ---------------- host launcher ----------------------------------------------
static float* sym_addr(const void* sym) {
    void* p = nullptr;
    cudaGetSymbolAddress(&p, sym);
    return (float*)p;
}

extern "C" void kernel_launch(void* const* d_in, const int* in_sizes, int n_in,
                              void* d_out, int out_size)
{
    const float* x0     = (const float*)d_in[0];
    const float* x1     = (const float*)d_in[1];
    const float* x2     = (const float*)d_in[2];
    const float* w0     = (const float*)d_in[3];
    const float* b0     = (const float*)d_in[4];
    const float* w1     = (const float*)d_in[5];
    const float* b1     = (const float*)d_in[6];
    const float* w2     = (const float*)d_in[7];
    const float* b2     = (const float*)d_in[8];
    const float* bases1 = (const float*)d_in[9];
    const float* comp1  = (const float*)d_in[10];
    const float* root1  = (const float*)d_in[11];
    const float* bias1  = (const float*)d_in[12];
    const float* bases2 = (const float*)d_in[13];
    const float* comp2  = (const float*)d_in[14];
    const float* root2  = (const float*)d_in[15];
    const float* bias2  = (const float*)d_in[16];
    const int*   ei     = (const int*)d_in[17];
    const int*   et     = (const int*)d_in[18];
    int E = in_sizes[18];
    const int* srcp = ei;
    const int* dstp = ei + E;

    float* ph   = sym_addr(g_h);
    float* pB1  = sym_addr(g_B1);
    float* pb1e = sym_addr(g_bias1e);
    float* pz1  = sym_addr(g_z1);
    float* pB2  = sym_addr(g_B2);
    float* pb2e = sym_addr(g_bias2e);
    float* pz2  = sym_addr(g_z2);

    // init / counts
    k_zero_cnt<<<(RC * NTOT + 255) / 256, 256>>>();
    k_build_B1<<<(128 * 448 + 255) / 256, 256>>>(comp1, bases1, root1, bias1);
    k_build_B2<<<(64 * 112 + 255) / 256, 256>>>(comp2, bases2, root2, bias2);
    k_count<<<(E + 255) / 256, 256>>>(dstp, et, E);
    k_invc<<<(RC * NTOT + 255) / 256, 256>>>();

    // projections -> g_h   (C = X * W^T + b)
    {
        dim3 g(2, (30000 + 127) / 128);
        k_gemm<<<g, 256>>>(30000, 128, 256, x0, 256, w0, 256, ph, 128, b0, 1);
    }
    {
        dim3 g(2, (50000 + 127) / 128);
        k_gemm<<<g, 256>>>(50000, 128, 512, x1, 512, w1, 512, ph + (size_t)30000 * 128, 128, b1, 1);
    }
    {
        dim3 g(2, (20000 + 127) / 128);
        k_gemm<<<g, 256>>>(20000, 128, 128, x2, 128, w2, 128, ph + (size_t)80000 * 128, 128, b2, 1);
    }

    // layer 1: z1 = h @ [W1 | root1] + [0 | bias1]
    {
        dim3 g(7, (NTOT + 127) / 128);
        k_gemm<<<g, 256>>>(NTOT, 448, 128, ph, 128, pB1, 448, pz1, 448, pb1e, 0);
    }
    k_scatter1<<<(E * 16 + 255) / 256, 256>>>(srcp, dstp, et, E);

    // layer 2: z2 = y1 @ [W2 | root2] + [0 | bias2]   (y1 = z1 cols 384..447)
    {
        dim3 g(2, (NTOT + 127) / 128);
        k_gemm<<<g, 256>>>(NTOT, 112, 64, pz1 + 384, 448, pB2, 112, pz2, 112, pb2e, 0);
    }
    k_scatter2<<<(E * 4 + 255) / 256, 256>>>(srcp, dstp, et, E);

    // softmax -> d_out
    k_softmax<<<(N0C + 255) / 256, 256>>>((float*)d_out);
}

// round 13
// speedup vs baseline: 1.4113x; 1.4113x over previous
#include <cuda_runtime.h>
#include <cuda_bf16.h>
#include <cstdint>
#include <math.h>

// Problem constants (fixed by the dataset)
#define NTOT 100000
#define N0C  30000
#define RC   6

// ---------------- scratch (device globals; no allocations allowed) ------------
__device__ __align__(128) float g_h [(size_t)NTOT * 128];   // projected features
__device__ __align__(128) float g_B1t[448 * 128];           // [W1(r) | root1] as [N=448][K=128]
__device__ __align__(128) float g_bias1e[448];
__device__ __align__(128) float g_z1[(size_t)NTOT * 448];   // cols 0..383 xt, 384..447 layer-1 out
__device__ __align__(128) float g_B2t[112 * 64];            // [W2(r) | root2] as [N=112][K=64]
__device__ __align__(128) float g_bias2e[112];
__device__ __align__(128) float g_z2[(size_t)NTOT * 112];   // cols 0..95 xt, 96..111 layer-2 out
__device__ __align__(128) int   g_cnt [RC * NTOT];
__device__ __align__(128) float g_invc[RC * NTOT];

__device__ __forceinline__ uint32_t smem_u32(const void* p) {
    uint32_t a;
    asm("{ .reg .u64 t; cvta.to.shared.u64 t, %1; cvt.u32.u64 %0, t; }" : "=r"(a) : "l"(p));
    return a;
}

// ---------------- tiny init kernels ------------------------------------------
__global__ void k_zero_cnt() {
    int i = blockIdx.x * 256 + threadIdx.x;
    if (i < RC * NTOT) g_cnt[i] = 0;
}

// B1t[c][k]  (c<384: W1[r=c/64][k][c%64], else root1[k][c-384])
__global__ void k_build_B1(const float* __restrict__ comp1, const float* __restrict__ bases1,
                           const float* __restrict__ root1, const float* __restrict__ bias1) {
    int i = blockIdx.x * 256 + threadIdx.x;
    if (i >= 448 * 128) return;
    int c = i / 128, k = i % 128;
    float v;
    if (c < 384) {
        int r = c >> 6, o = c & 63;
        float s = 0.f;
        #pragma unroll
        for (int b = 0; b < 30; b++) s += comp1[r * 30 + b] * bases1[b * 8192 + k * 64 + o];
        v = s;
    } else v = root1[k * 64 + (c - 384)];
    g_B1t[c * 128 + k] = v;
    if (k == 0) g_bias1e[c] = (c < 384) ? 0.f : bias1[c - 384];
}

__global__ void k_build_B2(const float* __restrict__ comp2, const float* __restrict__ bases2,
                           const float* __restrict__ root2, const float* __restrict__ bias2) {
    int i = blockIdx.x * 256 + threadIdx.x;
    if (i >= 112 * 64) return;
    int c = i / 64, k = i % 64;
    float v;
    if (c < 96) {
        int r = c >> 4, o = c & 15;
        float s = 0.f;
        #pragma unroll
        for (int b = 0; b < 30; b++) s += comp2[r * 30 + b] * bases2[b * 1024 + k * 16 + o];
        v = s;
    } else v = root2[k * 16 + (c - 96)];
    g_B2t[c * 64 + k] = v;
    if (k == 0) g_bias2e[c] = (c < 96) ? 0.f : bias2[c - 96];
}

__global__ void k_count(const int* __restrict__ dst, const int* __restrict__ et, int E) {
    int e = blockIdx.x * 256 + threadIdx.x;
    if (e >= E) return;
    atomicAdd(&g_cnt[et[e] * NTOT + dst[e]], 1);
}

__global__ void k_invc() {
    int i = blockIdx.x * 256 + threadIdx.x;
    if (i >= RC * NTOT) return;
    int c = g_cnt[i];
    g_invc[i] = 1.0f / (float)(c > 0 ? c : 1);
}

// ---------------- mma.sync split-bf16 GEMM (arch-agnostic PTX) ----------------
// C[M,N] = A[M,K] (fp32) * B[N,K]^T (fp32) + bias, computed as
// D = Ahi*Bhi + Ahi*Blo + Alo*Bhi with mma.sync.m16n8k16 bf16 / fp32 accum.
// CTA: 128x64 tile, 256 thr = 8 warps (4 m x 2 n), warp = 32x32.
__device__ __forceinline__ void bf16_split2(float a, float b, uint32_t& hi, uint32_t& lo) {
    __nv_bfloat16 ha = __float2bfloat16_rn(a);
    __nv_bfloat16 hb = __float2bfloat16_rn(b);
    float ra = a - __bfloat162float(ha);
    float rb = b - __bfloat162float(hb);
    __nv_bfloat16 la = __float2bfloat16_rn(ra);
    __nv_bfloat16 lb = __float2bfloat16_rn(rb);
    hi = ((uint32_t)*(uint16_t*)&hb << 16) | (uint32_t)*(uint16_t*)&ha;
    lo = ((uint32_t)*(uint16_t*)&lb << 16) | (uint32_t)*(uint16_t*)&la;
}

#define LDSM4(r, ad) \
    asm volatile("ldmatrix.sync.aligned.m8n8.x4.shared.b16 {%0,%1,%2,%3}, [%4];" \
        : "=r"((r)[0]), "=r"((r)[1]), "=r"((r)[2]), "=r"((r)[3]) : "r"(ad))

#define MMA16816(c, a, b0, b1) \
    asm volatile("mma.sync.aligned.m16n8k16.row.col.f32.bf16.bf16.f32 " \
        "{%0,%1,%2,%3}, {%4,%5,%6,%7}, {%8,%9}, {%0,%1,%2,%3};" \
        : "+f"((c)[0]), "+f"((c)[1]), "+f"((c)[2]), "+f"((c)[3]) \
        : "r"((a)[0]), "r"((a)[1]), "r"((a)[2]), "r"((a)[3]), "r"(b0), "r"(b1))

__global__ __launch_bounds__(256) void k_gemm_mma(
    int M, int N, int K,
    const float* __restrict__ A, int lda,
    const float* __restrict__ B, int ldb,
    float* __restrict__ C, int ldc,
    const float* __restrict__ bias)
{
    // 48KB static SMEM: A hi/lo 128x64 bf16 (16KB each), B hi/lo 64x64 bf16 (8KB each)
    __shared__ __align__(1024) char smb[49152];
    const uint32_t A_HI = 0, A_LO = 16384, B_HI = 32768, B_LO = 40960;
    uint32_t sb = smem_u32(smb);

    int tid = threadIdx.x, wid = tid >> 5, lane = tid & 31;
    int rowBase = blockIdx.x * 128;
    int n0 = blockIdx.y * 64;
    int warpM = wid & 3, warpN = wid >> 2;

    float acc[2][4][4];
    #pragma unroll
    for (int mt = 0; mt < 2; mt++)
        #pragma unroll
        for (int nt = 0; nt < 4; nt++)
            #pragma unroll
            for (int i = 0; i < 4; i++) acc[mt][nt][i] = 0.f;

    int nkc = K >> 6;
    for (int kc = 0; kc < nkc; kc++) {
        // ---- A tile: 128 rows x 64 K fp32 -> hi/lo bf16, SW128 swizzled ----
        #pragma unroll 2
        for (int idx = tid; idx < 128 * 16; idx += 256) {
            int r = idx >> 4, q = idx & 15;
            int gr = rowBase + r;
            float4 v = make_float4(0.f, 0.f, 0.f, 0.f);
            if (gr < M) v = *(const float4*)(A + (size_t)gr * lda + kc * 64 + q * 4);
            uint32_t off = (uint32_t)r * 128 + q * 8;
            uint32_t sw = off ^ ((off >> 3) & 0x70);
            uint2 h, l;
            bf16_split2(v.x, v.y, h.x, l.x);
            bf16_split2(v.z, v.w, h.y, l.y);
            *(uint2*)(smb + A_HI + sw) = h;
            *(uint2*)(smb + A_LO + sw) = l;
        }
        // ---- B tile: 64 rows x 64 K (zero-fill rows >= N) ----
        for (int idx = tid; idx < 64 * 16; idx += 256) {
            int r = idx >> 4, q = idx & 15;
            float4 v = make_float4(0.f, 0.f, 0.f, 0.f);
            if (n0 + r < N) v = *(const float4*)(B + (size_t)(n0 + r) * ldb + kc * 64 + q * 4);
            uint32_t off = (uint32_t)r * 128 + q * 8;
            uint32_t sw = off ^ ((off >> 3) & 0x70);
            uint2 h, l;
            bf16_split2(v.x, v.y, h.x, l.x);
            bf16_split2(v.z, v.w, h.y, l.y);
            *(uint2*)(smb + B_HI + sw) = h;
            *(uint2*)(smb + B_LO + sw) = l;
        }
        __syncthreads();

        // ---- compute: 3 passes (hi*hi, hi*lo, lo*hi), 4 k16 steps each ----
        #pragma unroll
        for (int p = 0; p < 3; p++) {
            uint32_t Ab = sb + ((p == 2) ? A_LO : A_HI);
            uint32_t Bb = sb + ((p == 1) ? B_LO : B_HI);
            #pragma unroll
            for (int k16 = 0; k16 < 4; k16++) {
                int kc8 = k16 * 2;   // chunk index of k within row (16B chunks of 8 bf16)
                uint32_t a[2][4], br[2][4];
                #pragma unroll
                for (int mt = 0; mt < 2; mt++) {
                    int row = warpM * 32 + mt * 16 + (lane & 15);
                    int c = kc8 + (lane >> 4);
                    uint32_t ad = Ab + row * 128 + ((c ^ (row & 7)) << 4);
                    LDSM4(a[mt], ad);
                }
                #pragma unroll
                for (int nh = 0; nh < 2; nh++) {
                    int row = warpN * 32 + nh * 16 + (lane & 15);
                    int c = kc8 + (lane >> 4);
                    uint32_t bd = Bb + row * 128 + ((c ^ (row & 7)) << 4);
                    LDSM4(br[nh], bd);
                }
                #pragma unroll
                for (int mt = 0; mt < 2; mt++) {
                    MMA16816(acc[mt][0], a[mt], br[0][0], br[0][2]);
                    MMA16816(acc[mt][1], a[mt], br[0][1], br[0][3]);
                    MMA16816(acc[mt][2], a[mt], br[1][0], br[1][2]);
                    MMA16816(acc[mt][3], a[mt], br[1][1], br[1][3]);
                }
            }
        }
        __syncthreads();
    }

    // ---- epilogue: regs -> +bias -> C ----
    #pragma unroll
    for (int mt = 0; mt < 2; mt++) {
        #pragma unroll
        for (int nt = 0; nt < 4; nt++) {
            int cn = n0 + warpN * 32 + nt * 8 + 2 * (lane & 3);
            if (cn < N) {
                float b0v = bias[cn], b1v = bias[cn + 1];
                int r0 = rowBase + warpM * 32 + mt * 16 + (lane >> 2);
                if (r0 < M) {
                    float2 o = make_float2(acc[mt][nt][0] + b0v, acc[mt][nt][1] + b1v);
                    *(float2*)(C + (size_t)r0 * ldc + cn) = o;
                }
                int r1 = r0 + 8;
                if (r1 < M) {
                    float2 o = make_float2(acc[mt][nt][2] + b0v, acc[mt][nt][3] + b1v);
                    *(float2*)(C + (size_t)r1 * ldc + cn) = o;
                }
            }
        }
    }
}

// ---------------- edge scatter (mean folded in via 1/cnt) ---------------------
__global__ __launch_bounds__(256) void k_scatter1(
    const int* __restrict__ src, const int* __restrict__ dst,
    const int* __restrict__ et, int E)
{
    int gid = blockIdx.x * 256 + threadIdx.x;
    int e = gid >> 4;
    if (e >= E) return;
    int q = gid & 15;
    int s = src[e], d = dst[e], r = et[e];
    float ic = g_invc[r * NTOT + d];
    float4 v = *(const float4*)(g_z1 + (size_t)s * 448 + r * 64 + q * 4);
    float* p = g_z1 + (size_t)d * 448 + 384 + q * 4;
    asm volatile("red.global.add.v4.f32 [%0], {%1,%2,%3,%4};"
                 :: "l"(p), "f"(v.x * ic), "f"(v.y * ic), "f"(v.z * ic), "f"(v.w * ic)
                 : "memory");
}

__global__ __launch_bounds__(256) void k_scatter2(
    const int* __restrict__ src, const int* __restrict__ dst,
    const int* __restrict__ et, int E)
{
    int gid = blockIdx.x * 256 + threadIdx.x;
    int e = gid >> 2;
    if (e >= E) return;
    int d = dst[e];
    if (d >= N0C) return;
    int q = gid & 3;
    int s = src[e], r = et[e];
    float ic = g_invc[r * NTOT + d];
    float4 v = *(const float4*)(g_z2 + (size_t)s * 112 + r * 16 + q * 4);
    float* p = g_z2 + (size_t)d * 112 + 96 + q * 4;
    asm volatile("red.global.add.v4.f32 [%0], {%1,%2,%3,%4};"
                 :: "l"(p), "f"(v.x * ic), "f"(v.y * ic), "f"(v.z * ic), "f"(v.w * ic)
                 : "memory");
}

// ---------------- softmax over the 16 logits of the first 30000 rows ----------
__global__ void k_softmax(float* __restrict__ out) {
    int n = blockIdx.x * 256 + threadIdx.x;
    if (n >= N0C) return;
    const float* row = g_z2 + (size_t)n * 112 + 96;
    float v[16];
    #pragma unroll
    for (int j = 0; j < 16; j += 4) {
        float4 t = *(const float4*)(row + j);
        v[j] = t.x; v[j + 1] = t.y; v[j + 2] = t.z; v[j + 3] = t.w;
    }
    float m = v[0];
    #pragma unroll
    for (int j = 1; j < 16; j++) m = fmaxf(m, v[j]);
    float s = 0.f;
    #pragma unroll
    for (int j = 0; j < 16; j++) { v[j] = expf(v[j] - m); s += v[j]; }
    float is = 1.f / s;
    #pragma unroll
    for (int j = 0; j < 16; j += 4) {
        float4 o = make_float4(v[j] * is, v[j + 1] * is, v[j + 2] * is, v[j + 3] * is);
        *(float4*)(out + (size_t)n * 16 + j) = o;
    }
}

// ---------------- host launcher ----------------------------------------------
static float* sym_addr(const void* sym) {
    void* p = nullptr;
    cudaGetSymbolAddress(&p, sym);
    return (float*)p;
}

static void gemm_tc(int M, int N, int K, const float* A, int lda,
                    const float* B, int ldb, float* C, int ldc, const float* bias)
{
    dim3 g((M + 127) / 128, (N + 63) / 64);
    k_gemm_mma<<<g, 256>>>(M, N, K, A, lda, B, ldb, C, ldc, bias);
}

extern "C" void kernel_launch(void* const* d_in, const int* in_sizes, int n_in,
                              void* d_out, int out_size)
{
    const float* x0     = (const float*)d_in[0];
    const float* x1     = (const float*)d_in[1];
    const float* x2     = (const float*)d_in[2];
    const float* w0     = (const float*)d_in[3];
    const float* b0     = (const float*)d_in[4];
    const float* w1     = (const float*)d_in[5];
    const float* b1     = (const float*)d_in[6];
    const float* w2     = (const float*)d_in[7];
    const float* b2     = (const float*)d_in[8];
    const float* bases1 = (const float*)d_in[9];
    const float* comp1  = (const float*)d_in[10];
    const float* root1  = (const float*)d_in[11];
    const float* bias1  = (const float*)d_in[12];
    const float* bases2 = (const float*)d_in[13];
    const float* comp2  = (const float*)d_in[14];
    const float* root2  = (const float*)d_in[15];
    const float* bias2  = (const float*)d_in[16];
    const int*   ei     = (const int*)d_in[17];
    const int*   et     = (const int*)d_in[18];
    int E = in_sizes[18];
    const int* srcp = ei;
    const int* dstp = ei + E;

    float* ph   = sym_addr(g_h);
    float* pB1  = sym_addr(g_B1t);
    float* pb1e = sym_addr(g_bias1e);
    float* pz1  = sym_addr(g_z1);
    float* pB2  = sym_addr(g_B2t);
    float* pb2e = sym_addr(g_bias2e);
    float* pz2  = sym_addr(g_z2);

    // init / counts
    k_zero_cnt<<<(RC * NTOT + 255) / 256, 256>>>();
    k_build_B1<<<(448 * 128 + 255) / 256, 256>>>(comp1, bases1, root1, bias1);
    k_build_B2<<<(112 * 64 + 255) / 256, 256>>>(comp2, bases2, root2, bias2);
    k_count<<<(E + 255) / 256, 256>>>(dstp, et, E);
    k_invc<<<(RC * NTOT + 255) / 256, 256>>>();

    // projections: h = x @ W^T + b   (W already [N=128][K] row-major)
    gemm_tc(30000, 128, 256, x0, 256, w0, 256, ph, 128, b0);
    gemm_tc(50000, 128, 512, x1, 512, w1, 512, ph + (size_t)30000 * 128, 128, b1);
    gemm_tc(20000, 128, 128, x2, 128, w2, 128, ph + (size_t)80000 * 128, 128, b2);

    // layer 1: z1 = h @ [W1 | root1]^T_stored + [0 | bias1]
    gemm_tc(NTOT, 448, 128, ph, 128, pB1, 128, pz1, 448, pb1e);
    k_scatter1<<<(E * 16 + 255) / 256, 256>>>(srcp, dstp, et, E);

    // layer 2: z2 = y1 @ [W2 | root2]^T_stored + [0 | bias2]  (y1 = z1 cols 384..447)
    gemm_tc(NTOT, 112, 64, pz1 + 384, 448, pB2, 64, pz2, 112, pb2e);
    k_scatter2<<<(E * 4 + 255) / 256, 256>>>(srcp, dstp, et, E);

    // softmax -> d_out
    k_softmax<<<(N0C + 255) / 256, 256>>>((float*)d_out);
}